// round 7
// baseline (speedup 1.0000x reference)
#include <cuda_runtime.h>
#include <cuda_bf16.h>
#include <cstdint>

#define NUM 16
#define DIM 128
#define NN (NUM*DIM)            // 2048
#define BATCH 4096
#define INC 512
#define OUTC 512
#define STEPS 10
#define KE 6144                 // 3 segments of 2048 (step chain)
#define KEF 1536                // 3 segments of 512  (final GEMM)
#define KSPLIT 16
#define KC2 384                 // per-CTA K slice (KE/KSPLIT)
#define LDB_W 196               // Bs row stride in 32-bit words (384/2 + 4 pad)
#define SMEM_B (128*LDB_W*4)    // 100352 bytes

// ---------------- device scratch ----------------
__device__ __align__(16) __nv_bfloat16 g_Text[NN*KE];        // [Thi|Thi|Tlo], 25MB
__device__ __align__(16) __nv_bfloat16 g_Rt[2][DIM*KE];      // [Rhi|Rlo|Rhi] transposed
__device__ __align__(16) float g_P[KSPLIT*NN*DIM];           // split-K partials, 16.8MB
__device__ __align__(16) float g_S[NN*DIM];                  // sum R_0..R_9
__device__ __align__(16) float g_Rf[NN*DIM];                 // latest R (fp32)
__device__ __align__(16) __nv_bfloat16 g_Iext[BATCH*KEF];    // [Ihi|Ihi|Ilo], 12.6MB
__device__ __align__(16) __nv_bfloat16 g_Gext[OUTC*KEF];     // rows q: [Ghi|Glo|Ghi] over p
__device__ __align__(16) float g_beta[NN];
__device__ __align__(16) float g_h[DIM];
__device__ __align__(16) float g_WpostT[DIM*OUTC];
__device__ __align__(16) float g_T1[DIM*OUTC];
__device__ __align__(16) float g_G[INC*OUTC];
__device__ __align__(16) float g_dvec[OUTC];

// ---------------- raw mma helper ----------------
__device__ __forceinline__ void mma16816(float* d, const uint32_t* a, uint32_t b0, uint32_t b1) {
    asm volatile(
        "mma.sync.aligned.m16n8k16.row.col.f32.bf16.bf16.f32 "
        "{%0,%1,%2,%3}, {%4,%5,%6,%7}, {%8,%9}, {%0,%1,%2,%3};"
        : "+f"(d[0]), "+f"(d[1]), "+f"(d[2]), "+f"(d[3])
        : "r"(a[0]), "r"(a[1]), "r"(a[2]), "r"(a[3]), "r"(b0), "r"(b1));
}

// ---------------- GEMM body: Out[128,128] = A[128, nch*384] @ B[128, nch*384]^T ------------
// A streamed from global into fragments (no smem); B resident in smem per 384-chunk.
// 256 threads, 8 warps, warp tile 32x64, barrier-free inner loop.
__device__ __forceinline__ void gemm_mma(const __nv_bfloat16* __restrict__ Ag, long ldA,
                                         const __nv_bfloat16* __restrict__ Bg, long ldB,
                                         int nch, float* __restrict__ Out, long ldo) {
    extern __shared__ __align__(16) uint32_t Bs_w[];          // [128][LDB_W] words
    const int tid = threadIdx.x, wid = tid >> 5, lane = tid & 31;
    const int g = lane >> 2, tc = lane & 3;
    const int wr0 = (wid & 3) * 32;                           // warp rows
    const int wc0 = (wid >> 2) * 64;                          // warp cols

    float acc[2][8][4];
#pragma unroll
    for (int f = 0; f < 2; f++)
#pragma unroll
        for (int nf = 0; nf < 8; nf++)
#pragma unroll
            for (int v = 0; v < 4; v++) acc[f][nf][v] = 0.f;

    // A row pointers (4 rows per thread: frag f uses [2f], [2f+1])
    const __nv_bfloat16* pA[4];
    pA[0] = Ag + (long)(wr0 + g)*ldA;
    pA[1] = Ag + (long)(wr0 + g + 8)*ldA;
    pA[2] = Ag + (long)(wr0 + 16 + g)*ldA;
    pA[3] = Ag + (long)(wr0 + 16 + g + 8)*ldA;

    // B smem word addresses per n-fragment
    uint32_t bAddr[8];
#pragma unroll
    for (int nf = 0; nf < 8; nf++)
        bAddr[nf] = (uint32_t)(wc0 + nf*8 + g)*LDB_W + tc;

    const int total = nch * 24;
    uint32_t ap[2][2][4];

    // prefetch A for kt = 0, 1
#pragma unroll
    for (int pk = 0; pk < 2; pk++) {
        int k = pk*16 + tc*2;
#pragma unroll
        for (int f = 0; f < 2; f++) {
            ap[pk][f][0] = *(const uint32_t*)(pA[2*f]     + k);
            ap[pk][f][1] = *(const uint32_t*)(pA[2*f + 1] + k);
            ap[pk][f][2] = *(const uint32_t*)(pA[2*f]     + k + 8);
            ap[pk][f][3] = *(const uint32_t*)(pA[2*f + 1] + k + 8);
        }
    }

    for (int ch = 0; ch < nch; ch++) {
        __syncthreads();                                      // prior chunk's Bs reads done
        {   // fill Bs: 128 rows x 384 cols; 2 threads per row
            const int row = tid >> 1, half = (tid & 1)*192;
            const __nv_bfloat16* src = Bg + (long)row*ldB + (long)ch*KC2 + half;
            uint32_t* dst = Bs_w + row*LDB_W + half/2;
#pragma unroll
            for (int u = 0; u < 24; u++)
                *(uint4*)(dst + u*4) = *(const uint4*)(src + u*8);
        }
        __syncthreads();
#pragma unroll 4
        for (int kk = 0; kk < 24; kk++) {
            const int kt = ch*24 + kk;
            const uint32_t (*a)[4] = ap[kt & 1];
            const int kbw = kk*8;
#pragma unroll
            for (int nf = 0; nf < 8; nf++) {
                uint32_t b0 = Bs_w[bAddr[nf] + kbw];
                uint32_t b1 = Bs_w[bAddr[nf] + kbw + 4];
                mma16816(acc[0][nf], a[0], b0, b1);
                mma16816(acc[1][nf], a[1], b0, b1);
            }
            // prefetch A for kt+2 into the slot just consumed
            if (kt + 2 < total) {
                int k = (kt + 2)*16 + tc*2;
                uint32_t (*d)[4] = ap[kt & 1];
#pragma unroll
                for (int f = 0; f < 2; f++) {
                    d[f][0] = *(const uint32_t*)(pA[2*f]     + k);
                    d[f][1] = *(const uint32_t*)(pA[2*f + 1] + k);
                    d[f][2] = *(const uint32_t*)(pA[2*f]     + k + 8);
                    d[f][3] = *(const uint32_t*)(pA[2*f + 1] + k + 8);
                }
            }
        }
    }
#pragma unroll
    for (int f = 0; f < 2; f++) {
        const int row0 = wr0 + f*16 + g;
#pragma unroll
        for (int nf = 0; nf < 8; nf++) {
            const int col = wc0 + nf*8 + tc*2;
            *(float2*)(Out + (long)row0*ldo + col)       = make_float2(acc[f][nf][0], acc[f][nf][1]);
            *(float2*)(Out + (long)(row0 + 8)*ldo + col) = make_float2(acc[f][nf][2], acc[f][nf][3]);
        }
    }
}

// step MMA: partial[ks] = T_ext[mtile, ks slice] @ Rt[cur][:, ks slice]^T
__global__ void __launch_bounds__(256, 2) k_mma_step(int cur) {
    const int ks = blockIdx.x, mt = blockIdx.y;
    gemm_mma(g_Text + (size_t)mt*128*KE + ks*KC2, KE,
             g_Rt[cur] + ks*KC2, KE, 1,
             g_P + ((size_t)ks*NN + mt*128)*DIM, DIM);
}

// final MMA: out = I_ext @ G_ext^T
__global__ void __launch_bounds__(256, 2) k_mma_fin(float* __restrict__ out) {
    const int qt = blockIdx.x, bt = blockIdx.y;
    gemm_mma(g_Iext + (size_t)bt*128*KEF, KEF,
             g_Gext + (size_t)qt*128*KEF, KEF, 4,
             out + (size_t)bt*128*OUTC + qt*128, OUTC);
}

// out[b][q] += dvec[q]
__global__ void k_bias(float* __restrict__ out) {
    int idx = blockIdx.x*256 + threadIdx.x;
    int q4 = idx & (OUTC/4 - 1);
    float4 v = *(float4*)&out[idx*4];
    float4 d = *(const float4*)&g_dvec[q4*4];
    v.x += d.x; v.y += d.y; v.z += d.z; v.w += d.w;
    *(float4*)&out[idx*4] = v;
}

// ---------------- prep kernels (unchanged from passing R6) ----------------

__global__ void k_prep(const float* __restrict__ life, const float* __restrict__ bl) {
    int j = blockIdx.x, g = threadIdx.x;
    float s = 0.f;
#pragma unroll
    for (int i = 0; i < NUM; i++) {
        float gt = fmaxf(life[i*NUM + j], 0.f);
        s += gt * bl[(i*NUM + j)*DIM + g];
    }
    g_beta[j*DIM + g] = s;
}

__global__ void k_transpose(const float* __restrict__ Wpost) {
    int e = blockIdx.x, q = threadIdx.x;
    g_WpostT[e*OUTC + q] = Wpost[q*DIM + e];
}

__global__ void k_make_T(const float* __restrict__ W, const float* __restrict__ life) {
    const int j = blockIdx.x, i = blockIdx.y;
    const float gate = fmaxf(life[i*NUM + j], 0.f);
    const float* __restrict__ Wb = W + (size_t)(i*NUM + j)*DIM*DIM;   // [g][f]
    __shared__ float sm[32][DIM + 1];
    const int tid = threadIdx.x;
    for (int g0 = 0; g0 < DIM; g0 += 32) {
        for (int u = tid; u < 32*DIM; u += 256) {
            int gg = u >> 7, f = u & 127;
            sm[gg][f] = Wb[(size_t)(g0 + gg)*DIM + f];
        }
        __syncthreads();
#pragma unroll
        for (int it = 0; it < 8; it++) {
            int pi = it*256 + tid;
            int f = pi >> 4, gp = (pi & 15) * 2;
            float x0 = gate * sm[gp][f];
            float x1 = gate * sm[gp + 1][f];
            __nv_bfloat16 h0 = __float2bfloat16(x0);
            __nv_bfloat16 h1 = __float2bfloat16(x1);
            __nv_bfloat162 hv; hv.x = h0; hv.y = h1;
            __nv_bfloat162 lv;
            lv.x = __float2bfloat16(x0 - __bfloat162float(h0));
            lv.y = __float2bfloat16(x1 - __bfloat162float(h1));
            size_t row = (size_t)(i*DIM + f)*KE;
            int col = j*DIM + g0 + gp;
            *(__nv_bfloat162*)&g_Text[row + col]        = hv;
            *(__nv_bfloat162*)&g_Text[row + 2048 + col] = hv;
            *(__nv_bfloat162*)&g_Text[row + 4096 + col] = lv;
        }
        __syncthreads();
    }
}

__global__ void k_initRS() {
    int r = blockIdx.x, e = threadIdx.x;     // grid 2048 x 128
    g_S[(size_t)r*DIM + e] = (r == (NN - DIM) + e) ? 1.f : 0.f;
    if (r < DIM) {
#pragma unroll
        for (int it = 0; it < 24; it++) {
            int cp = (it*128 + e) * 2;
            int seg = cp >> 11, cc = cp & 2047;
            float v0 = ((seg == 0 || seg == 2) && cc     == (NN - DIM) + r) ? 1.f : 0.f;
            float v1 = ((seg == 0 || seg == 2) && cc + 1 == (NN - DIM) + r) ? 1.f : 0.f;
            __nv_bfloat162 v; v.x = __float2bfloat16(v0); v.y = __float2bfloat16(v1);
            *(__nv_bfloat162*)&g_Rt[0][(size_t)r*KE + cp] = v;
        }
    }
}

__global__ void k_reduce2(int cur, int addS) {
    const int mt = blockIdx.x, sl = blockIdx.y;
    const int base_r = mt*128 + sl*32;
    __shared__ float slab[32][DIM + 1];
    const int tid = threadIdx.x;
    for (int u = tid; u < 32*DIM; u += 256) {
        int rr = u >> 7, e = u & 127;
        float v = 0.f;
#pragma unroll
        for (int k = 0; k < KSPLIT; k++)
            v += g_P[(size_t)k*NN*DIM + (size_t)(base_r + rr)*DIM + e];
        g_Rf[(size_t)(base_r + rr)*DIM + e] = v;
        if (addS) g_S[(size_t)(base_r + rr)*DIM + e] += v;
        slab[rr][e] = v;
    }
    __syncthreads();
    int e = tid >> 1, hh = tid & 1;
    __nv_bfloat16* Rt = g_Rt[cur ^ 1];
#pragma unroll
    for (int k = 0; k < 16; k++) {
        int rr = hh*16 + k;
        float v = slab[rr][e];
        __nv_bfloat16 h = __float2bfloat16(v);
        __nv_bfloat16 l = __float2bfloat16(v - __bfloat162float(h));
        int col = base_r + rr;
        Rt[(size_t)e*KE + col]        = h;   // seg0: Rhi (pairs Thi)
        Rt[(size_t)e*KE + 2048 + col] = l;   // seg1: Rlo (pairs Thi)
        Rt[(size_t)e*KE + 4096 + col] = h;   // seg2: Rhi (pairs Tlo)
    }
}

__global__ void k_h(const float* __restrict__ bpre) {
    int e = blockIdx.x, tid = threadIdx.x;
    float s = 0.f;
    for (int r = tid; r < NN; r += 256) s += g_beta[r] * g_S[(size_t)r*DIM + e];
    if (tid < DIM) s += bpre[tid] * g_Rf[(size_t)tid*DIM + e];
    __shared__ float red[256];
    red[tid] = s;
    __syncthreads();
    for (int off = 128; off > 0; off >>= 1) {
        if (tid < off) red[tid] += red[tid + off];
        __syncthreads();
    }
    if (tid == 0) g_h[e] = red[0];
}

__global__ void k_T1() {
    int d = blockIdx.y;
    int q = blockIdx.x*128 + threadIdx.x;
    const float* __restrict__ Er = g_Rf + (size_t)d*DIM;
    float acc = 0.f;
#pragma unroll 8
    for (int e = 0; e < DIM; e++) acc += Er[e] * g_WpostT[e*OUTC + q];
    g_T1[d*OUTC + q] = acc;
}

__global__ void k_G(const float* __restrict__ Wpre) {
    int p = blockIdx.y;
    int q = blockIdx.x*128 + threadIdx.x;
    float acc = 0.f;
#pragma unroll 8
    for (int d = 0; d < DIM; d++) acc += Wpre[d*INC + p] * g_T1[d*OUTC + q];
    g_G[p*OUTC + q] = acc;
}

__global__ void k_dvec(const float* __restrict__ bpost) {
    int q = blockIdx.x*128 + threadIdx.x;
    float acc = bpost[q];
#pragma unroll 8
    for (int e = 0; e < DIM; e++) acc += g_h[e] * g_WpostT[e*OUTC + q];
    g_dvec[q] = acc;
}

__global__ void k_split_inp(const float* __restrict__ inp) {
    int b = blockIdx.x, tid = threadIdx.x;
#pragma unroll
    for (int it = 0; it < 2; it++) {
        int qp = (it*128 + tid) * 2;
        float2 x = *(const float2*)&inp[(size_t)b*INC + qp];
        __nv_bfloat16 h0 = __float2bfloat16(x.x);
        __nv_bfloat16 h1 = __float2bfloat16(x.y);
        __nv_bfloat162 hv; hv.x = h0; hv.y = h1;
        __nv_bfloat162 lv;
        lv.x = __float2bfloat16(x.x - __bfloat162float(h0));
        lv.y = __float2bfloat16(x.y - __bfloat162float(h1));
        size_t ro = (size_t)b*KEF;
        *(__nv_bfloat162*)&g_Iext[ro + qp]        = hv;
        *(__nv_bfloat162*)&g_Iext[ro + 512 + qp]  = hv;
        *(__nv_bfloat162*)&g_Iext[ro + 1024 + qp] = lv;
    }
}

__global__ void k_split_G() {
    int q = blockIdx.x;
    for (int p = threadIdx.x; p < INC; p += 128) {
        float x = g_G[(size_t)p*OUTC + q];
        __nv_bfloat16 h = __float2bfloat16(x);
        __nv_bfloat16 l = __float2bfloat16(x - __bfloat162float(h));
        size_t ro = (size_t)q*KEF;
        g_Gext[ro + p]        = h;
        g_Gext[ro + 512 + p]  = l;
        g_Gext[ro + 1024 + p] = h;
    }
}

// ---------------- launch ----------------
extern "C" void kernel_launch(void* const* d_in, const int* in_sizes, int n_in,
                              void* d_out, int out_size) {
    (void)in_sizes; (void)n_in; (void)out_size;
    const float* inp   = (const float*)d_in[0];
    const float* Wpre  = (const float*)d_in[1];
    const float* bpre  = (const float*)d_in[2];
    const float* W     = (const float*)d_in[3];
    const float* bl    = (const float*)d_in[4];
    const float* life  = (const float*)d_in[5];
    const float* Wpost = (const float*)d_in[6];
    const float* bpost = (const float*)d_in[7];
    float* out = (float*)d_out;

    cudaFuncSetAttribute(k_mma_step, cudaFuncAttributeMaxDynamicSharedMemorySize, SMEM_B);
    cudaFuncSetAttribute(k_mma_fin,  cudaFuncAttributeMaxDynamicSharedMemorySize, SMEM_B);

    k_make_T<<<dim3(NUM, NUM), 256>>>(W, life);          // idx 0
    k_initRS<<<NN, DIM>>>();                             // idx 1
    k_prep<<<NUM, DIM>>>(life, bl);                      // idx 2

    int cur = 0;
    for (int s = 0; s < STEPS; s++) {
        k_mma_step<<<dim3(KSPLIT, NUM), 256, SMEM_B>>>(cur);  // first one = idx 3 (profiled 5)
        k_reduce2<<<dim3(NUM, 4), 256>>>(cur, (s < STEPS - 1) ? 1 : 0);
        cur ^= 1;
    }

    k_h<<<DIM, 256>>>(bpre);
    k_transpose<<<DIM, OUTC>>>(Wpost);
    k_T1<<<dim3(OUTC/128, DIM), 128>>>();
    k_G<<<dim3(OUTC/128, INC), 128>>>(Wpre);
    k_dvec<<<OUTC/128, 128>>>(bpost);
    k_split_inp<<<BATCH, 128>>>(inp);
    k_split_G<<<OUTC, 128>>>();
    k_mma_fin<<<dim3(OUTC/128, BATCH/128), 256, SMEM_B>>>(out);
    k_bias<<<BATCH*OUTC/1024, 256>>>(out);
}

// round 8
// speedup vs baseline: 1.1496x; 1.1496x over previous
#include <cuda_runtime.h>
#include <cuda_bf16.h>
#include <cstdint>

#define NUM 16
#define DIM 128
#define NN (NUM*DIM)            // 2048
#define BATCH 4096
#define INC 512
#define OUTC 512
#define STEPS 10
#define KE 6144                 // 3 segments of 2048 (step chain)
#define KEF 1536                // 3 segments of 512  (final GEMM)
#define KSPLIT 16
#define KC2 384                 // per-CTA K slice (KE/KSPLIT)
#define RSW 24                  // smem row stride in words (16 data + 8 pad; ≡24 mod 32)
#define STG_W (128*RSW*2)       // words per stage (A+B) = 6144
#define SMEM_BYTES (4*STG_W*4)  // 98304

// ---------------- device scratch ----------------
__device__ __align__(16) __nv_bfloat16 g_Text[NN*KE];        // [Thi|Thi|Tlo], k16-permuted
__device__ __align__(16) __nv_bfloat16 g_Rt[2][DIM*KE];      // [Rhi|Rlo|Rhi], k16-permuted
__device__ __align__(16) float g_P[KSPLIT*NN*DIM];           // split-K partials
__device__ __align__(16) float g_S[NN*DIM];
__device__ __align__(16) float g_Rf[NN*DIM];
__device__ __align__(16) __nv_bfloat16 g_Iext[BATCH*KEF];    // [Ihi|Ihi|Ilo], permuted
__device__ __align__(16) __nv_bfloat16 g_Gext[OUTC*KEF];     // [Ghi|Glo|Ghi], permuted
__device__ __align__(16) float g_beta[NN];
__device__ __align__(16) float g_h[DIM];
__device__ __align__(16) float g_WpostT[DIM*OUTC];
__device__ __align__(16) float g_T1[DIM*OUTC];
__device__ __align__(16) float g_G[INC*OUTC];
__device__ __align__(16) float g_dvec[OUTC];

// ---------------- helpers ----------------
// word perm within k16 group: orig word i -> new pos ((i&3)<<1)|(i>>2)
__device__ __forceinline__ int permw(int i) { return ((i & 3) << 1) | (i >> 2); }
__device__ __forceinline__ int invw(int ni) { return ((ni & 1) << 2) | (ni >> 1); }

__device__ __forceinline__ void mma16816(float* d, const uint32_t* a, uint32_t b0, uint32_t b1) {
    asm volatile(
        "mma.sync.aligned.m16n8k16.row.col.f32.bf16.bf16.f32 "
        "{%0,%1,%2,%3}, {%4,%5,%6,%7}, {%8,%9}, {%0,%1,%2,%3};"
        : "+f"(d[0]), "+f"(d[1]), "+f"(d[2]), "+f"(d[3])
        : "r"(a[0]), "r"(a[1]), "r"(a[2]), "r"(a[3]), "r"(b0), "r"(b1));
}
__device__ __forceinline__ void cpa16(uint32_t saddr, const void* g) {
    asm volatile("cp.async.ca.shared.global [%0], [%1], 16;" :: "r"(saddr), "l"(g));
}
__device__ __forceinline__ void cpa_commit() { asm volatile("cp.async.commit_group;" ::: "memory"); }
template<int N> __device__ __forceinline__ void cpa_wait() {
    asm volatile("cp.async.wait_group %0;" :: "n"(N) : "memory");
}
__device__ __forceinline__ uint32_t smem_u32(const void* p) {
    uint32_t a;
    asm("{ .reg .u64 t; cvta.to.shared.u64 t, %1; cvt.u32.u64 %0, t; }" : "=r"(a) : "l"(p));
    return a;
}

// ---------------- GEMM body: Out[128,128] = A[128, nch*32] @ B[128, nch*32]^T -------------
// cp.async 4-stage pipeline, fragments via conflict-free lds.64 (permuted global layout).
__device__ __forceinline__ void gemm_cp(const __nv_bfloat16* __restrict__ Ag, long ldA,
                                        const __nv_bfloat16* __restrict__ Bg, long ldB,
                                        int nch, float* __restrict__ Out, long ldo) {
    extern __shared__ __align__(16) uint32_t sm[];
    const uint32_t sbase = smem_u32(sm);
    const int tid = threadIdx.x, wid = tid >> 5, lane = tid & 31;
    const int g = lane >> 2, tc = lane & 3;
    const int wr0 = (wid & 3) * 32, wc0 = (wid >> 2) * 64;

    float acc[2][8][4];
#pragma unroll
    for (int f = 0; f < 2; f++)
#pragma unroll
        for (int nf = 0; nf < 8; nf++)
#pragma unroll
            for (int v = 0; v < 4; v++) acc[f][nf][v] = 0.f;

    const int Lr = tid >> 1, c0 = (tid & 1) * 2;     // load mapping: 2 rows/thread-pair
    const int aOff = (wr0 + g)*RSW + tc*2;
    const int bOff = (wc0 + g)*RSW + tc*2;

#define LOAD_STAGE(c) do {                                                        \
        int _s = (c) & 3;                                                         \
        const __nv_bfloat16* _ga = Ag + (long)Lr*ldA + (long)(c)*32 + c0*8;       \
        uint32_t _da = sbase + (uint32_t)((_s*STG_W + Lr*RSW + c0*4) * 4);        \
        cpa16(_da, _ga); cpa16(_da + 16, _ga + 8);                                \
        const __nv_bfloat16* _gb = Bg + (long)Lr*ldB + (long)(c)*32 + c0*8;       \
        uint32_t _db = _da + 128*RSW*4;                                           \
        cpa16(_db, _gb); cpa16(_db + 16, _gb + 8);                                \
        cpa_commit();                                                             \
    } while (0)

    LOAD_STAGE(0); LOAD_STAGE(1); LOAD_STAGE(2);

    for (int ch = 0; ch < nch; ch++) {
        const int rem = nch - 1 - ch;
        if (rem >= 2) cpa_wait<2>(); else if (rem == 1) cpa_wait<1>(); else cpa_wait<0>();
        __syncthreads();
        if (ch + 3 < nch) LOAD_STAGE(ch + 3);
        const uint32_t* sA = sm + (ch & 3)*STG_W;
        const uint32_t* sB = sA + 128*RSW;
#pragma unroll
        for (int k16 = 0; k16 < 2; k16++) {
            const int kw = k16*8;
            uint32_t a[2][4];
#pragma unroll
            for (int f = 0; f < 2; f++) {
                uint2 A0 = *(const uint2*)(sA + aOff + f*16*RSW + kw);
                uint2 A1 = *(const uint2*)(sA + aOff + (f*16 + 8)*RSW + kw);
                a[f][0] = A0.x; a[f][1] = A1.x; a[f][2] = A0.y; a[f][3] = A1.y;
            }
#pragma unroll
            for (int nf = 0; nf < 8; nf++) {
                uint2 Bv = *(const uint2*)(sB + bOff + nf*8*RSW + kw);
                mma16816(acc[0][nf], a[0], Bv.x, Bv.y);
                mma16816(acc[1][nf], a[1], Bv.x, Bv.y);
            }
        }
    }
#undef LOAD_STAGE
#pragma unroll
    for (int f = 0; f < 2; f++) {
        const int row0 = wr0 + f*16 + g;
#pragma unroll
        for (int nf = 0; nf < 8; nf++) {
            const int col = wc0 + nf*8 + tc*2;
            *(float2*)(Out + (long)row0*ldo + col)       = make_float2(acc[f][nf][0], acc[f][nf][1]);
            *(float2*)(Out + (long)(row0 + 8)*ldo + col) = make_float2(acc[f][nf][2], acc[f][nf][3]);
        }
    }
}

// step MMA: partial[ks] = T_ext[mtile, ks slice] @ Rt[cur][:, ks slice]^T
__global__ void __launch_bounds__(256, 2) k_mma_step(int cur) {
    const int ks = blockIdx.x, mt = blockIdx.y;
    gemm_cp(g_Text + (size_t)mt*128*KE + ks*KC2, KE,
            g_Rt[cur] + ks*KC2, KE, KC2/32,
            g_P + ((size_t)ks*NN + mt*128)*DIM, DIM);
}

// final MMA: out = I_ext @ G_ext^T
__global__ void __launch_bounds__(256, 2) k_mma_fin(float* __restrict__ out) {
    const int qt = blockIdx.x, bt = blockIdx.y;
    gemm_cp(g_Iext + (size_t)bt*128*KEF, KEF,
            g_Gext + (size_t)qt*128*KEF, KEF, KEF/32,
            out + (size_t)bt*128*OUTC + qt*128, OUTC);
}

// out[b][q] += dvec[q]
__global__ void k_bias(float* __restrict__ out) {
    int idx = blockIdx.x*256 + threadIdx.x;
    int q4 = idx & (OUTC/4 - 1);
    float4 v = *(float4*)&out[idx*4];
    float4 d = *(const float4*)&g_dvec[q4*4];
    v.x += d.x; v.y += d.y; v.z += d.z; v.w += d.w;
    *(float4*)&out[idx*4] = v;
}

// ---------------- prep kernels ----------------

__global__ void k_prep(const float* __restrict__ life, const float* __restrict__ bl) {
    int j = blockIdx.x, g = threadIdx.x;
    float s = 0.f;
#pragma unroll
    for (int i = 0; i < NUM; i++) {
        float gt = fmaxf(life[i*NUM + j], 0.f);
        s += gt * bl[(i*NUM + j)*DIM + g];
    }
    g_beta[j*DIM + g] = s;
}

__global__ void k_transpose(const float* __restrict__ Wpost) {
    int e = blockIdx.x, q = threadIdx.x;
    g_WpostT[e*OUTC + q] = Wpost[q*DIM + e];
}

// T_ext split [Thi|Thi|Tlo], k16-word-permuted columns
__global__ void k_make_T(const float* __restrict__ W, const float* __restrict__ life) {
    const int j = blockIdx.x, i = blockIdx.y;
    const float gate = fmaxf(life[i*NUM + j], 0.f);
    const float* __restrict__ Wb = W + (size_t)(i*NUM + j)*DIM*DIM;   // [g][f]
    __shared__ float sm[32][DIM + 1];
    const int tid = threadIdx.x;
    for (int g0 = 0; g0 < DIM; g0 += 32) {
        for (int u = tid; u < 32*DIM; u += 256) {
            int gg = u >> 7, f = u & 127;
            sm[gg][f] = Wb[(size_t)(g0 + gg)*DIM + f];
        }
        __syncthreads();
#pragma unroll
        for (int it = 0; it < 8; it++) {
            int pi = it*256 + tid;
            int f = pi >> 4, gp = (pi & 15) * 2;
            float x0 = gate * sm[gp][f];
            float x1 = gate * sm[gp + 1][f];
            __nv_bfloat16 h0 = __float2bfloat16(x0);
            __nv_bfloat16 h1 = __float2bfloat16(x1);
            __nv_bfloat162 hv; hv.x = h0; hv.y = h1;
            __nv_bfloat162 lv;
            lv.x = __float2bfloat16(x0 - __bfloat162float(h0));
            lv.y = __float2bfloat16(x1 - __bfloat162float(h1));
            size_t row = (size_t)(i*DIM + f)*KE;
            int col = j*DIM + g0 + gp;
            int nc = (col & ~15) | (permw((col & 15) >> 1) << 1);
            *(__nv_bfloat162*)&g_Text[row + nc]        = hv;
            *(__nv_bfloat162*)&g_Text[row + 2048 + nc] = hv;
            *(__nv_bfloat162*)&g_Text[row + 4096 + nc] = lv;
        }
        __syncthreads();
    }
}

// Rt[0] identity (permuted), S = R_0
__global__ void k_initRS() {
    int r = blockIdx.x, e = threadIdx.x;     // grid 2048 x 128
    g_S[(size_t)r*DIM + e] = (r == (NN - DIM) + e) ? 1.f : 0.f;
    if (r < DIM) {
#pragma unroll
        for (int it = 0; it < 24; it++) {
            int cp = (it*128 + e) * 2;       // NEW col pair
            float vv[2];
#pragma unroll
            for (int u = 0; u < 2; u++) {
                int c = cp + u;
                int oc = (c & ~15) | (invw((c >> 1) & 7) << 1) | (c & 1);   // orig col
                int seg = oc >> 11, cc = oc & 2047;
                vv[u] = ((seg == 0 || seg == 2) && cc == (NN - DIM) + r) ? 1.f : 0.f;
            }
            __nv_bfloat162 v; v.x = __float2bfloat16(vv[0]); v.y = __float2bfloat16(vv[1]);
            *(__nv_bfloat162*)&g_Rt[0][(size_t)r*KE + cp] = v;
        }
    }
}

// reduce split-K partials -> Rf, S accum, re-split (permuted) into Rt[cur^1]
__global__ void k_reduce2(int cur, int addS) {
    const int mt = blockIdx.x, sl = blockIdx.y;
    const int base_r = mt*128 + sl*32;
    __shared__ float slab[32][DIM + 1];
    const int tid = threadIdx.x;
    for (int u = tid; u < 32*DIM; u += 256) {
        int rr = u >> 7, e = u & 127;
        float v = 0.f;
#pragma unroll
        for (int k = 0; k < KSPLIT; k++)
            v += g_P[(size_t)k*NN*DIM + (size_t)(base_r + rr)*DIM + e];
        g_Rf[(size_t)(base_r + rr)*DIM + e] = v;
        if (addS) g_S[(size_t)(base_r + rr)*DIM + e] += v;
        slab[rr][e] = v;
    }
    __syncthreads();
    int e = tid >> 1, hh = tid & 1;
    __nv_bfloat16* Rt = g_Rt[cur ^ 1];
#pragma unroll
    for (int k = 0; k < 16; k++) {
        int rr = hh*16 + k;
        float v = slab[rr][e];
        __nv_bfloat16 h = __float2bfloat16(v);
        __nv_bfloat16 l = __float2bfloat16(v - __bfloat162float(h));
        int col = base_r + rr;                       // col & 15 == k
        int nc = (col & ~15) | (permw(k >> 1) << 1) | (k & 1);
        Rt[(size_t)e*KE + nc]        = h;   // seg0: Rhi (pairs Thi)
        Rt[(size_t)e*KE + 2048 + nc] = l;   // seg1: Rlo (pairs Thi)
        Rt[(size_t)e*KE + 4096 + nc] = h;   // seg2: Rhi (pairs Tlo)
    }
}

// ---------------- combine kernels ----------------
__global__ void k_h(const float* __restrict__ bpre) {
    int e = blockIdx.x, tid = threadIdx.x;
    float s = 0.f;
    for (int r = tid; r < NN; r += 256) s += g_beta[r] * g_S[(size_t)r*DIM + e];
    if (tid < DIM) s += bpre[tid] * g_Rf[(size_t)tid*DIM + e];
    __shared__ float red[256];
    red[tid] = s;
    __syncthreads();
    for (int off = 128; off > 0; off >>= 1) {
        if (tid < off) red[tid] += red[tid + off];
        __syncthreads();
    }
    if (tid == 0) g_h[e] = red[0];
}

__global__ void k_T1() {
    int d = blockIdx.y;
    int q = blockIdx.x*128 + threadIdx.x;
    const float* __restrict__ Er = g_Rf + (size_t)d*DIM;
    float acc = 0.f;
#pragma unroll 8
    for (int e = 0; e < DIM; e++) acc += Er[e] * g_WpostT[e*OUTC + q];
    g_T1[d*OUTC + q] = acc;
}

__global__ void k_G(const float* __restrict__ Wpre) {
    int p = blockIdx.y;
    int q = blockIdx.x*128 + threadIdx.x;
    float acc = 0.f;
#pragma unroll 8
    for (int d = 0; d < DIM; d++) acc += Wpre[d*INC + p] * g_T1[d*OUTC + q];
    g_G[p*OUTC + q] = acc;
}

__global__ void k_dvec(const float* __restrict__ bpost) {
    int q = blockIdx.x*128 + threadIdx.x;
    float acc = bpost[q];
#pragma unroll 8
    for (int e = 0; e < DIM; e++) acc += g_h[e] * g_WpostT[e*OUTC + q];
    g_dvec[q] = acc;
}

// inp -> [Ihi|Ihi|Ilo], permuted
__global__ void k_split_inp(const float* __restrict__ inp) {
    int b = blockIdx.x, tid = threadIdx.x;
#pragma unroll
    for (int it = 0; it < 2; it++) {
        int qp = (it*128 + tid) * 2;
        float2 x = *(const float2*)&inp[(size_t)b*INC + qp];
        __nv_bfloat16 h0 = __float2bfloat16(x.x);
        __nv_bfloat16 h1 = __float2bfloat16(x.y);
        __nv_bfloat162 hv; hv.x = h0; hv.y = h1;
        __nv_bfloat162 lv;
        lv.x = __float2bfloat16(x.x - __bfloat162float(h0));
        lv.y = __float2bfloat16(x.y - __bfloat162float(h1));
        int nc = (qp & ~15) | (permw((qp & 15) >> 1) << 1);
        size_t ro = (size_t)b*KEF;
        *(__nv_bfloat162*)&g_Iext[ro + nc]        = hv;
        *(__nv_bfloat162*)&g_Iext[ro + 512 + nc]  = hv;
        *(__nv_bfloat162*)&g_Iext[ro + 1024 + nc] = lv;
    }
}

// Gext row q over p: [hi|lo|hi] of G[p][q], permuted
__global__ void k_split_G() {
    int q = blockIdx.x;
    for (int p = threadIdx.x; p < INC; p += 128) {
        float x = g_G[(size_t)p*OUTC + q];
        __nv_bfloat16 h = __float2bfloat16(x);
        __nv_bfloat16 l = __float2bfloat16(x - __bfloat162float(h));
        int nc = (p & ~15) | (permw((p & 15) >> 1) << 1) | (p & 1);
        size_t ro = (size_t)q*KEF;
        g_Gext[ro + nc]        = h;
        g_Gext[ro + 512 + nc]  = l;
        g_Gext[ro + 1024 + nc] = h;
    }
}

// ---------------- launch ----------------
extern "C" void kernel_launch(void* const* d_in, const int* in_sizes, int n_in,
                              void* d_out, int out_size) {
    (void)in_sizes; (void)n_in; (void)out_size;
    const float* inp   = (const float*)d_in[0];
    const float* Wpre  = (const float*)d_in[1];
    const float* bpre  = (const float*)d_in[2];
    const float* W     = (const float*)d_in[3];
    const float* bl    = (const float*)d_in[4];
    const float* life  = (const float*)d_in[5];
    const float* Wpost = (const float*)d_in[6];
    const float* bpost = (const float*)d_in[7];
    float* out = (float*)d_out;

    cudaFuncSetAttribute(k_mma_step, cudaFuncAttributeMaxDynamicSharedMemorySize, SMEM_BYTES);
    cudaFuncSetAttribute(k_mma_fin,  cudaFuncAttributeMaxDynamicSharedMemorySize, SMEM_BYTES);

    k_make_T<<<dim3(NUM, NUM), 256>>>(W, life);          // idx 0
    k_initRS<<<NN, DIM>>>();                             // idx 1
    k_prep<<<NUM, DIM>>>(life, bl);                      // idx 2

    int cur = 0;
    for (int s = 0; s < STEPS; s++) {
        k_mma_step<<<dim3(KSPLIT, NUM), 256, SMEM_BYTES>>>(cur);  // idx 3 first (profiled 5)
        k_reduce2<<<dim3(NUM, 4), 256>>>(cur, (s < STEPS - 1) ? 1 : 0);
        cur ^= 1;
    }

    k_h<<<DIM, 256>>>(bpre);
    k_transpose<<<DIM, OUTC>>>(Wpost);
    k_T1<<<dim3(OUTC/128, DIM), 128>>>();
    k_G<<<dim3(OUTC/128, INC), 128>>>(Wpre);
    k_dvec<<<OUTC/128, 128>>>(bpost);
    k_split_inp<<<BATCH, 128>>>(inp);
    k_split_G<<<OUTC, 128>>>();
    k_mma_fin<<<dim3(OUTC/128, BATCH/128), 256, SMEM_BYTES>>>(out);
    k_bias<<<BATCH*OUTC/1024, 256>>>(out);
}

// round 9
// speedup vs baseline: 1.4592x; 1.2693x over previous
#include <cuda_runtime.h>
#include <cuda_bf16.h>
#include <cstdint>

#define NUM 16
#define DIM 128
#define NN (NUM*DIM)            // 2048
#define BATCH 4096
#define INC 512
#define OUTC 512
#define STEPS 10
#define KE 6144                 // 3 segments of 2048 (step chain)
#define KEF 1536                // 3 segments of 512  (final GEMM)
#define KSPLIT 16
#define KC2 384                 // per-CTA K slice (KE/KSPLIT)
#define RSW 20                  // smem row stride in words (16 data + 4 pad)
#define STG_W (128*RSW*2)       // words per stage (A+B) = 5120
#define SMEM_BYTES (4*STG_W*4)  // 81920

// ---------------- device scratch ----------------
__device__ __align__(16) __nv_bfloat16 g_Text[NN*KE];        // [Thi|Thi|Tlo]
__device__ __align__(16) __nv_bfloat16 g_Rt[2][DIM*KE];      // [Rhi|Rlo|Rhi] transposed
__device__ __align__(16) float g_P[KSPLIT*NN*DIM];           // split-K partials
__device__ __align__(16) float g_S[NN*DIM];
__device__ __align__(16) float g_Rf[NN*DIM];
__device__ __align__(16) __nv_bfloat16 g_Iext[BATCH*KEF];    // [Ihi|Ihi|Ilo]
__device__ __align__(16) __nv_bfloat16 g_Gext[OUTC*KEF];     // rows q: [Ghi|Glo|Ghi] over p
__device__ __align__(16) float g_beta[NN];
__device__ __align__(16) float g_h[DIM];
__device__ __align__(16) float g_WpostT[DIM*OUTC];
__device__ __align__(16) float g_T1[DIM*OUTC];
__device__ __align__(16) float g_G[INC*OUTC];
__device__ __align__(16) float g_dvec[OUTC];

// ---------------- helpers ----------------
__device__ __forceinline__ void mma16816(float* d, const uint32_t* a, uint32_t b0, uint32_t b1) {
    asm volatile(
        "mma.sync.aligned.m16n8k16.row.col.f32.bf16.bf16.f32 "
        "{%0,%1,%2,%3}, {%4,%5,%6,%7}, {%8,%9}, {%0,%1,%2,%3};"
        : "+f"(d[0]), "+f"(d[1]), "+f"(d[2]), "+f"(d[3])
        : "r"(a[0]), "r"(a[1]), "r"(a[2]), "r"(a[3]), "r"(b0), "r"(b1));
}
__device__ __forceinline__ void ldsm4(uint32_t* r, uint32_t addr) {
    asm volatile("ldmatrix.sync.aligned.m8n8.x4.shared.b16 {%0,%1,%2,%3}, [%4];"
                 : "=r"(r[0]), "=r"(r[1]), "=r"(r[2]), "=r"(r[3]) : "r"(addr));
}
__device__ __forceinline__ void cpa16(uint32_t saddr, const void* g) {
    asm volatile("cp.async.ca.shared.global [%0], [%1], 16;" :: "r"(saddr), "l"(g));
}
__device__ __forceinline__ void cpa_commit() { asm volatile("cp.async.commit_group;" ::: "memory"); }
template<int N> __device__ __forceinline__ void cpa_wait() {
    asm volatile("cp.async.wait_group %0;" :: "n"(N) : "memory");
}
__device__ __forceinline__ uint32_t smem_u32(const void* p) {
    uint32_t a;
    asm("{ .reg .u64 t; cvta.to.shared.u64 t, %1; cvt.u32.u64 %0, t; }" : "=r"(a) : "l"(p));
    return a;
}

// ---------------- GEMM body: Out[128,128] = A[128, nch*32] @ B[128, nch*32]^T -------------
// cp.async 4-stage pipeline; fragments via conflict-free ldmatrix (RSW=20).
__device__ __forceinline__ void gemm_cp(const __nv_bfloat16* __restrict__ Ag, long ldA,
                                        const __nv_bfloat16* __restrict__ Bg, long ldB,
                                        int nch, float* __restrict__ Out, long ldo) {
    extern __shared__ __align__(16) uint32_t sm[];
    const uint32_t sbase = smem_u32(sm);
    const int tid = threadIdx.x, wid = tid >> 5, lane = tid & 31;
    const int g = lane >> 2, tc = lane & 3;
    const int wr0 = (wid & 3) * 32, wc0 = (wid >> 2) * 64;

    float acc[2][8][4];
#pragma unroll
    for (int f = 0; f < 2; f++)
#pragma unroll
        for (int nf = 0; nf < 8; nf++)
#pragma unroll
            for (int v = 0; v < 4; v++) acc[f][nf][v] = 0.f;

    // ldmatrix per-lane bases (word units within a stage)
    const int q = lane >> 3, r8 = lane & 7;
    int aBase[2], bBase[4];
#pragma unroll
    for (int f = 0; f < 2; f++)
        aBase[f] = (wr0 + f*16 + r8 + (q & 1)*8)*RSW + (q >> 1)*4;
#pragma unroll
    for (int n4 = 0; n4 < 4; n4++)
        bBase[n4] = (128 + wc0 + n4*16 + r8 + (q >> 1)*8)*RSW + (q & 1)*4;

    // cp.async mapping: 2 threads per row, 32B each
    const int Lr = tid >> 1, c0w = (tid & 1)*8;

#define LOAD_STAGE(c) do {                                                        \
        int _s = (c) & 3;                                                         \
        const __nv_bfloat16* _ga = Ag + (long)Lr*ldA + (long)(c)*32 + c0w*2;      \
        uint32_t _da = sbase + (uint32_t)((_s*STG_W + Lr*RSW + c0w) * 4);         \
        cpa16(_da, _ga); cpa16(_da + 16, _ga + 8);                                \
        const __nv_bfloat16* _gb = Bg + (long)Lr*ldB + (long)(c)*32 + c0w*2;      \
        uint32_t _db = _da + 128*RSW*4;                                           \
        cpa16(_db, _gb); cpa16(_db + 16, _gb + 8);                                \
        cpa_commit();                                                             \
    } while (0)

    LOAD_STAGE(0); LOAD_STAGE(1); LOAD_STAGE(2);

    for (int ch = 0; ch < nch; ch++) {
        const int rem = nch - 1 - ch;
        if (rem >= 2) cpa_wait<2>(); else if (rem == 1) cpa_wait<1>(); else cpa_wait<0>();
        __syncthreads();
        if (ch + 3 < nch) LOAD_STAGE(ch + 3);
        const uint32_t stg = sbase + (uint32_t)(((ch & 3)*STG_W) * 4);
#pragma unroll
        for (int k16 = 0; k16 < 2; k16++) {
            const uint32_t kw = k16*8*4;
            uint32_t a[2][4], bb[4][4];
            ldsm4(a[0], stg + aBase[0]*4 + kw);
            ldsm4(a[1], stg + aBase[1]*4 + kw);
#pragma unroll
            for (int n4 = 0; n4 < 4; n4++) ldsm4(bb[n4], stg + bBase[n4]*4 + kw);
#pragma unroll
            for (int n4 = 0; n4 < 4; n4++) {
                mma16816(acc[0][n4*2],     a[0], bb[n4][0], bb[n4][1]);
                mma16816(acc[1][n4*2],     a[1], bb[n4][0], bb[n4][1]);
                mma16816(acc[0][n4*2 + 1], a[0], bb[n4][2], bb[n4][3]);
                mma16816(acc[1][n4*2 + 1], a[1], bb[n4][2], bb[n4][3]);
            }
        }
    }
#undef LOAD_STAGE
#pragma unroll
    for (int f = 0; f < 2; f++) {
        const int row0 = wr0 + f*16 + g;
#pragma unroll
        for (int nf = 0; nf < 8; nf++) {
            const int col = wc0 + nf*8 + tc*2;
            *(float2*)(Out + (long)row0*ldo + col)       = make_float2(acc[f][nf][0], acc[f][nf][1]);
            *(float2*)(Out + (long)(row0 + 8)*ldo + col) = make_float2(acc[f][nf][2], acc[f][nf][3]);
        }
    }
}

// step MMA: partial[ks] = T_ext[mtile, ks slice] @ Rt[cur][:, ks slice]^T
__global__ void __launch_bounds__(256, 2) k_mma_step(int cur) {
    const int ks = blockIdx.x, mt = blockIdx.y;
    gemm_cp(g_Text + (size_t)mt*128*KE + ks*KC2, KE,
            g_Rt[cur] + ks*KC2, KE, KC2/32,
            g_P + ((size_t)ks*NN + mt*128)*DIM, DIM);
}

// final MMA: out = I_ext @ G_ext^T
__global__ void __launch_bounds__(256, 2) k_mma_fin(float* __restrict__ out) {
    const int qt = blockIdx.x, bt = blockIdx.y;
    gemm_cp(g_Iext + (size_t)bt*128*KEF, KEF,
            g_Gext + (size_t)qt*128*KEF, KEF, KEF/32,
            out + (size_t)bt*128*OUTC + qt*128, OUTC);
}

// out[b][q] += dvec[q]
__global__ void k_bias(float* __restrict__ out) {
    int idx = blockIdx.x*256 + threadIdx.x;
    int q4 = idx & (OUTC/4 - 1);
    float4 v = *(float4*)&out[idx*4];
    float4 d = *(const float4*)&g_dvec[q4*4];
    v.x += d.x; v.y += d.y; v.z += d.z; v.w += d.w;
    *(float4*)&out[idx*4] = v;
}

// ---------------- prep kernels (R6-passing, unpermuted) ----------------

__global__ void k_prep(const float* __restrict__ life, const float* __restrict__ bl) {
    int j = blockIdx.x, g = threadIdx.x;
    float s = 0.f;
#pragma unroll
    for (int i = 0; i < NUM; i++) {
        float gt = fmaxf(life[i*NUM + j], 0.f);
        s += gt * bl[(i*NUM + j)*DIM + g];
    }
    g_beta[j*DIM + g] = s;
}

__global__ void k_transpose(const float* __restrict__ Wpost) {
    int e = blockIdx.x, q = threadIdx.x;
    g_WpostT[e*OUTC + q] = Wpost[q*DIM + e];
}

__global__ void k_make_T(const float* __restrict__ W, const float* __restrict__ life) {
    const int j = blockIdx.x, i = blockIdx.y;
    const float gate = fmaxf(life[i*NUM + j], 0.f);
    const float* __restrict__ Wb = W + (size_t)(i*NUM + j)*DIM*DIM;   // [g][f]
    __shared__ float sm[32][DIM + 1];
    const int tid = threadIdx.x;
    for (int g0 = 0; g0 < DIM; g0 += 32) {
        for (int u = tid; u < 32*DIM; u += 256) {
            int gg = u >> 7, f = u & 127;
            sm[gg][f] = Wb[(size_t)(g0 + gg)*DIM + f];
        }
        __syncthreads();
#pragma unroll
        for (int it = 0; it < 8; it++) {
            int pi = it*256 + tid;
            int f = pi >> 4, gp = (pi & 15) * 2;
            float x0 = gate * sm[gp][f];
            float x1 = gate * sm[gp + 1][f];
            __nv_bfloat16 h0 = __float2bfloat16(x0);
            __nv_bfloat16 h1 = __float2bfloat16(x1);
            __nv_bfloat162 hv; hv.x = h0; hv.y = h1;
            __nv_bfloat162 lv;
            lv.x = __float2bfloat16(x0 - __bfloat162float(h0));
            lv.y = __float2bfloat16(x1 - __bfloat162float(h1));
            size_t row = (size_t)(i*DIM + f)*KE;
            int col = j*DIM + g0 + gp;
            *(__nv_bfloat162*)&g_Text[row + col]        = hv;
            *(__nv_bfloat162*)&g_Text[row + 2048 + col] = hv;
            *(__nv_bfloat162*)&g_Text[row + 4096 + col] = lv;
        }
        __syncthreads();
    }
}

__global__ void k_initRS() {
    int r = blockIdx.x, e = threadIdx.x;     // grid 2048 x 128
    g_S[(size_t)r*DIM + e] = (r == (NN - DIM) + e) ? 1.f : 0.f;
    if (r < DIM) {
#pragma unroll
        for (int it = 0; it < 24; it++) {
            int cp = (it*128 + e) * 2;
            int seg = cp >> 11, cc = cp & 2047;
            float v0 = ((seg == 0 || seg == 2) && cc     == (NN - DIM) + r) ? 1.f : 0.f;
            float v1 = ((seg == 0 || seg == 2) && cc + 1 == (NN - DIM) + r) ? 1.f : 0.f;
            __nv_bfloat162 v; v.x = __float2bfloat16(v0); v.y = __float2bfloat16(v1);
            *(__nv_bfloat162*)&g_Rt[0][(size_t)r*KE + cp] = v;
        }
    }
}

__global__ void k_reduce2(int cur, int addS) {
    const int mt = blockIdx.x, sl = blockIdx.y;
    const int base_r = mt*128 + sl*32;
    __shared__ float slab[32][DIM + 1];
    const int tid = threadIdx.x;
    for (int u = tid; u < 32*DIM; u += 256) {
        int rr = u >> 7, e = u & 127;
        float v = 0.f;
#pragma unroll
        for (int k = 0; k < KSPLIT; k++)
            v += g_P[(size_t)k*NN*DIM + (size_t)(base_r + rr)*DIM + e];
        g_Rf[(size_t)(base_r + rr)*DIM + e] = v;
        if (addS) g_S[(size_t)(base_r + rr)*DIM + e] += v;
        slab[rr][e] = v;
    }
    __syncthreads();
    int e = tid >> 1, hh = tid & 1;
    __nv_bfloat16* Rt = g_Rt[cur ^ 1];
#pragma unroll
    for (int k = 0; k < 16; k++) {
        int rr = hh*16 + k;
        float v = slab[rr][e];
        __nv_bfloat16 h = __float2bfloat16(v);
        __nv_bfloat16 l = __float2bfloat16(v - __bfloat162float(h));
        int col = base_r + rr;
        Rt[(size_t)e*KE + col]        = h;   // seg0: Rhi (pairs Thi)
        Rt[(size_t)e*KE + 2048 + col] = l;   // seg1: Rlo (pairs Thi)
        Rt[(size_t)e*KE + 4096 + col] = h;   // seg2: Rhi (pairs Tlo)
    }
}

__global__ void k_h(const float* __restrict__ bpre) {
    int e = blockIdx.x, tid = threadIdx.x;
    float s = 0.f;
    for (int r = tid; r < NN; r += 256) s += g_beta[r] * g_S[(size_t)r*DIM + e];
    if (tid < DIM) s += bpre[tid] * g_Rf[(size_t)tid*DIM + e];
    __shared__ float red[256];
    red[tid] = s;
    __syncthreads();
    for (int off = 128; off > 0; off >>= 1) {
        if (tid < off) red[tid] += red[tid + off];
        __syncthreads();
    }
    if (tid == 0) g_h[e] = red[0];
}

__global__ void k_T1() {
    int d = blockIdx.y;
    int q = blockIdx.x*128 + threadIdx.x;
    const float* __restrict__ Er = g_Rf + (size_t)d*DIM;
    float acc = 0.f;
#pragma unroll 8
    for (int e = 0; e < DIM; e++) acc += Er[e] * g_WpostT[e*OUTC + q];
    g_T1[d*OUTC + q] = acc;
}

__global__ void k_G(const float* __restrict__ Wpre) {
    int p = blockIdx.y;
    int q = blockIdx.x*128 + threadIdx.x;
    float acc = 0.f;
#pragma unroll 8
    for (int d = 0; d < DIM; d++) acc += Wpre[d*INC + p] * g_T1[d*OUTC + q];
    g_G[p*OUTC + q] = acc;
}

__global__ void k_dvec(const float* __restrict__ bpost) {
    int q = blockIdx.x*128 + threadIdx.x;
    float acc = bpost[q];
#pragma unroll 8
    for (int e = 0; e < DIM; e++) acc += g_h[e] * g_WpostT[e*OUTC + q];
    g_dvec[q] = acc;
}

__global__ void k_split_inp(const float* __restrict__ inp) {
    int b = blockIdx.x, tid = threadIdx.x;
#pragma unroll
    for (int it = 0; it < 2; it++) {
        int qp = (it*128 + tid) * 2;
        float2 x = *(const float2*)&inp[(size_t)b*INC + qp];
        __nv_bfloat16 h0 = __float2bfloat16(x.x);
        __nv_bfloat16 h1 = __float2bfloat16(x.y);
        __nv_bfloat162 hv; hv.x = h0; hv.y = h1;
        __nv_bfloat162 lv;
        lv.x = __float2bfloat16(x.x - __bfloat162float(h0));
        lv.y = __float2bfloat16(x.y - __bfloat162float(h1));
        size_t ro = (size_t)b*KEF;
        *(__nv_bfloat162*)&g_Iext[ro + qp]        = hv;
        *(__nv_bfloat162*)&g_Iext[ro + 512 + qp]  = hv;
        *(__nv_bfloat162*)&g_Iext[ro + 1024 + qp] = lv;
    }
}

__global__ void k_split_G() {
    int q = blockIdx.x;
    for (int p = threadIdx.x; p < INC; p += 128) {
        float x = g_G[(size_t)p*OUTC + q];
        __nv_bfloat16 h = __float2bfloat16(x);
        __nv_bfloat16 l = __float2bfloat16(x - __bfloat162float(h));
        size_t ro = (size_t)q*KEF;
        g_Gext[ro + p]        = h;
        g_Gext[ro + 512 + p]  = l;
        g_Gext[ro + 1024 + p] = h;
    }
}

// ---------------- launch ----------------
extern "C" void kernel_launch(void* const* d_in, const int* in_sizes, int n_in,
                              void* d_out, int out_size) {
    (void)in_sizes; (void)n_in; (void)out_size;
    const float* inp   = (const float*)d_in[0];
    const float* Wpre  = (const float*)d_in[1];
    const float* bpre  = (const float*)d_in[2];
    const float* W     = (const float*)d_in[3];
    const float* bl    = (const float*)d_in[4];
    const float* life  = (const float*)d_in[5];
    const float* Wpost = (const float*)d_in[6];
    const float* bpost = (const float*)d_in[7];
    float* out = (float*)d_out;

    cudaFuncSetAttribute(k_mma_step, cudaFuncAttributeMaxDynamicSharedMemorySize, SMEM_BYTES);
    cudaFuncSetAttribute(k_mma_fin,  cudaFuncAttributeMaxDynamicSharedMemorySize, SMEM_BYTES);

    k_make_T<<<dim3(NUM, NUM), 256>>>(W, life);          // idx 0
    k_initRS<<<NN, DIM>>>();                             // idx 1
    k_prep<<<NUM, DIM>>>(life, bl);                      // idx 2

    int cur = 0;
    for (int s = 0; s < STEPS; s++) {
        k_mma_step<<<dim3(KSPLIT, NUM), 256, SMEM_BYTES>>>(cur);  // idx 3 first (profiled 5)
        k_reduce2<<<dim3(NUM, 4), 256>>>(cur, (s < STEPS - 1) ? 1 : 0);
        cur ^= 1;
    }

    k_h<<<DIM, 256>>>(bpre);
    k_transpose<<<DIM, OUTC>>>(Wpost);
    k_T1<<<dim3(OUTC/128, DIM), 128>>>();
    k_G<<<dim3(OUTC/128, INC), 128>>>(Wpre);
    k_dvec<<<OUTC/128, 128>>>(bpost);
    k_split_inp<<<BATCH, 128>>>(inp);
    k_split_G<<<OUTC, 128>>>();
    k_mma_fin<<<dim3(OUTC/128, BATCH/128), 256, SMEM_BYTES>>>(out);
    k_bias<<<BATCH*OUTC/1024, 256>>>(out);
}

// round 10
// speedup vs baseline: 1.5316x; 1.0496x over previous
#include <cuda_runtime.h>
#include <cuda_bf16.h>
#include <cstdint>

#define NUM 16
#define DIM 128
#define NN (NUM*DIM)            // 2048
#define BATCH 4096
#define INC 512
#define OUTC 512
#define STEPS 10
#define KE 6144                 // 3 segments of 2048 (step chain)
#define KEF 1536                // 3 segments of 512  (final GEMM)
#define KSPLIT 8
#define KC2 768                 // per-CTA K slice (KE/KSPLIT)
#define BK 64
#define RSW 36                  // smem row stride in words (32 data + 4 pad; 36%32=4 -> conflict-free ldsm)
#define STG_W (128*RSW*2)       // words per stage (A+B) = 9216
#define SMEM_BYTES (4*STG_W*4)  // 147456

// ---------------- device scratch ----------------
__device__ __align__(16) __nv_bfloat16 g_Text[NN*KE];        // [Thi|Thi|Tlo]
__device__ __align__(16) __nv_bfloat16 g_Rt[2][DIM*KE];      // [Rhi|Rlo|Rhi] transposed
__device__ __align__(16) float g_P[KSPLIT*NN*DIM];           // split-K partials, 8.4MB
__device__ __align__(16) float g_S[NN*DIM];
__device__ __align__(16) float g_Rf[NN*DIM];
__device__ __align__(16) __nv_bfloat16 g_Iext[BATCH*KEF];    // [Ihi|Ihi|Ilo]
__device__ __align__(16) __nv_bfloat16 g_Gext[OUTC*KEF];     // rows q: [Ghi|Glo|Ghi] over p
__device__ __align__(16) float g_beta[NN];
__device__ __align__(16) float g_h[DIM];
__device__ __align__(16) float g_WpostT[DIM*OUTC];
__device__ __align__(16) float g_T1[DIM*OUTC];
__device__ __align__(16) float g_G[INC*OUTC];
__device__ __align__(16) float g_dvec[OUTC];

// ---------------- helpers ----------------
__device__ __forceinline__ void mma16816(float* d, const uint32_t* a, uint32_t b0, uint32_t b1) {
    asm volatile(
        "mma.sync.aligned.m16n8k16.row.col.f32.bf16.bf16.f32 "
        "{%0,%1,%2,%3}, {%4,%5,%6,%7}, {%8,%9}, {%0,%1,%2,%3};"
        : "+f"(d[0]), "+f"(d[1]), "+f"(d[2]), "+f"(d[3])
        : "r"(a[0]), "r"(a[1]), "r"(a[2]), "r"(a[3]), "r"(b0), "r"(b1));
}
__device__ __forceinline__ void ldsm4(uint32_t* r, uint32_t addr) {
    asm volatile("ldmatrix.sync.aligned.m8n8.x4.shared.b16 {%0,%1,%2,%3}, [%4];"
                 : "=r"(r[0]), "=r"(r[1]), "=r"(r[2]), "=r"(r[3]) : "r"(addr));
}
__device__ __forceinline__ void cpa16(uint32_t saddr, const void* g) {
    asm volatile("cp.async.ca.shared.global [%0], [%1], 16;" :: "r"(saddr), "l"(g));
}
__device__ __forceinline__ void cpa_commit() { asm volatile("cp.async.commit_group;" ::: "memory"); }
template<int N> __device__ __forceinline__ void cpa_wait() {
    asm volatile("cp.async.wait_group %0;" :: "n"(N) : "memory");
}
__device__ __forceinline__ uint32_t smem_u32(const void* p) {
    uint32_t a;
    asm("{ .reg .u64 t; cvta.to.shared.u64 t, %1; cvt.u32.u64 %0, t; }" : "=r"(a) : "l"(p));
    return a;
}

// ---------------- GEMM body: Out[128,128] = A[128, nch*64] @ B[128, nch*64]^T -------------
// 512 threads, 16 warps, warp tile 32x32; BK=64, 4-stage cp.async;
// fragment double-buffering across k16s; conflict-free ldmatrix (RSW=36).
template<bool BIAS>
__device__ __forceinline__ void gemm_cp(const __nv_bfloat16* __restrict__ Ag, long ldA,
                                        const __nv_bfloat16* __restrict__ Bg, long ldB,
                                        int nch, float* __restrict__ Out, long ldo,
                                        const float* __restrict__ bias) {
    extern __shared__ __align__(16) uint32_t sm[];
    const uint32_t sbase = smem_u32(sm);
    const int tid = threadIdx.x, wid = tid >> 5, lane = tid & 31;
    const int g = lane >> 2, tc = lane & 3;
    const int wr0 = (wid & 3) * 32, wc0 = (wid >> 2) * 32;

    float acc[2][4][4];
#pragma unroll
    for (int f = 0; f < 2; f++)
#pragma unroll
        for (int nf = 0; nf < 4; nf++)
#pragma unroll
            for (int v = 0; v < 4; v++) acc[f][nf][v] = 0.f;

    // ldmatrix per-lane bases (byte units within a stage)
    const int q = lane >> 3, r8 = lane & 7;
    uint32_t aB[2], bB[2];
#pragma unroll
    for (int f = 0; f < 2; f++)
        aB[f] = (uint32_t)(((wr0 + f*16 + r8 + (q & 1)*8)*RSW + (q >> 1)*4) * 4);
#pragma unroll
    for (int n4 = 0; n4 < 2; n4++)
        bB[n4] = (uint32_t)(((128 + wc0 + n4*16 + r8 + (q >> 1)*8)*RSW + (q & 1)*4) * 4);

    // cp.async mapping: 512 threads; tid<256 -> A rows, tid>=256 -> B rows; 64B/thread
    const int isB = tid >= 256, lt = tid & 255;
    const int Lr = lt >> 1, offw = (lt & 1)*16;
    const __nv_bfloat16* __restrict__ Gsrc = isB ? Bg : Ag;
    const long ldS = isB ? ldB : ldA;
    const uint32_t dBase = sbase + (uint32_t)(((isB ? 128*RSW : 0) + Lr*RSW + offw) * 4);

#define LOAD_STAGE(c) do {                                                        \
        const __nv_bfloat16* _g = Gsrc + (long)Lr*ldS + (long)(c)*BK + offw*2;    \
        uint32_t _d = dBase + (uint32_t)((((c) & 3)*STG_W) * 4);                  \
        cpa16(_d, _g); cpa16(_d + 16, _g + 8);                                    \
        cpa16(_d + 32, _g + 16); cpa16(_d + 48, _g + 24);                         \
        cpa_commit();                                                             \
    } while (0)

    LOAD_STAGE(0); LOAD_STAGE(1); LOAD_STAGE(2);

    uint32_t af[2][2][4], bf[2][2][4];

#define LD_FR(kk, buf, stg) do {                                                  \
        uint32_t _kw = (uint32_t)((kk)*32);                                       \
        ldsm4(af[buf][0], (stg) + aB[0] + _kw);                                   \
        ldsm4(af[buf][1], (stg) + aB[1] + _kw);                                   \
        ldsm4(bf[buf][0], (stg) + bB[0] + _kw);                                   \
        ldsm4(bf[buf][1], (stg) + bB[1] + _kw);                                   \
    } while (0)

#define DO_MMA(buf) do {                                                          \
        _Pragma("unroll")                                                         \
        for (int n4 = 0; n4 < 2; n4++) {                                          \
            mma16816(acc[0][n4*2],     af[buf][0], bf[buf][n4][0], bf[buf][n4][1]); \
            mma16816(acc[1][n4*2],     af[buf][1], bf[buf][n4][0], bf[buf][n4][1]); \
            mma16816(acc[0][n4*2 + 1], af[buf][0], bf[buf][n4][2], bf[buf][n4][3]); \
            mma16816(acc[1][n4*2 + 1], af[buf][1], bf[buf][n4][2], bf[buf][n4][3]); \
        }                                                                         \
    } while (0)

    for (int ch = 0; ch < nch; ch++) {
        const int rem = nch - 1 - ch;
        if (rem >= 2) cpa_wait<2>(); else if (rem == 1) cpa_wait<1>(); else cpa_wait<0>();
        __syncthreads();
        if (ch + 3 < nch) LOAD_STAGE(ch + 3);
        const uint32_t stg = sbase + (uint32_t)(((ch & 3)*STG_W) * 4);
        LD_FR(0, 0, stg);
        LD_FR(1, 1, stg);
        DO_MMA(0);
        LD_FR(2, 0, stg);
        DO_MMA(1);
        LD_FR(3, 1, stg);
        DO_MMA(0);
        DO_MMA(1);
    }
#undef LOAD_STAGE
#undef LD_FR
#undef DO_MMA
#pragma unroll
    for (int f = 0; f < 2; f++) {
        const int row0 = wr0 + f*16 + g;
#pragma unroll
        for (int nf = 0; nf < 4; nf++) {
            const int col = wc0 + nf*8 + tc*2;
            float2 v0 = make_float2(acc[f][nf][0], acc[f][nf][1]);
            float2 v1 = make_float2(acc[f][nf][2], acc[f][nf][3]);
            if (BIAS) {
                float2 d = *(const float2*)&bias[col];
                v0.x += d.x; v0.y += d.y; v1.x += d.x; v1.y += d.y;
            }
            *(float2*)(Out + (long)row0*ldo + col)       = v0;
            *(float2*)(Out + (long)(row0 + 8)*ldo + col) = v1;
        }
    }
}

// step MMA: partial[ks] = T_ext[mtile, ks slice] @ Rt[cur][:, ks slice]^T
__global__ void __launch_bounds__(512, 1) k_mma_step(int cur) {
    const int ks = blockIdx.x, mt = blockIdx.y;
    gemm_cp<false>(g_Text + (size_t)mt*128*KE + ks*KC2, KE,
                   g_Rt[cur] + ks*KC2, KE, KC2/BK,
                   g_P + ((size_t)ks*NN + mt*128)*DIM, DIM, nullptr);
}

// final MMA: out = I_ext @ G_ext^T + dvec (bias fused)
__global__ void __launch_bounds__(512, 1) k_mma_fin(float* __restrict__ out) {
    const int qt = blockIdx.x, bt = blockIdx.y;
    gemm_cp<true>(g_Iext + (size_t)bt*128*KEF, KEF,
                  g_Gext + (size_t)qt*128*KEF, KEF, KEF/BK,
                  out + (size_t)bt*128*OUTC + qt*128, OUTC, g_dvec + qt*128);
}

// ---------------- prep kernels (R9-passing) ----------------

__global__ void k_prep(const float* __restrict__ life, const float* __restrict__ bl) {
    int j = blockIdx.x, g = threadIdx.x;
    float s = 0.f;
#pragma unroll
    for (int i = 0; i < NUM; i++) {
        float gt = fmaxf(life[i*NUM + j], 0.f);
        s += gt * bl[(i*NUM + j)*DIM + g];
    }
    g_beta[j*DIM + g] = s;
}

__global__ void k_transpose(const float* __restrict__ Wpost) {
    int e = blockIdx.x, q = threadIdx.x;
    g_WpostT[e*OUTC + q] = Wpost[q*DIM + e];
}

__global__ void k_make_T(const float* __restrict__ W, const float* __restrict__ life) {
    const int j = blockIdx.x, i = blockIdx.y;
    const float gate = fmaxf(life[i*NUM + j], 0.f);
    const float* __restrict__ Wb = W + (size_t)(i*NUM + j)*DIM*DIM;   // [g][f]
    __shared__ float sm[32][DIM + 1];
    const int tid = threadIdx.x;
    for (int g0 = 0; g0 < DIM; g0 += 32) {
        for (int u = tid; u < 32*DIM; u += 256) {
            int gg = u >> 7, f = u & 127;
            sm[gg][f] = Wb[(size_t)(g0 + gg)*DIM + f];
        }
        __syncthreads();
#pragma unroll
        for (int it = 0; it < 8; it++) {
            int pi = it*256 + tid;
            int f = pi >> 4, gp = (pi & 15) * 2;
            float x0 = gate * sm[gp][f];
            float x1 = gate * sm[gp + 1][f];
            __nv_bfloat16 h0 = __float2bfloat16(x0);
            __nv_bfloat16 h1 = __float2bfloat16(x1);
            __nv_bfloat162 hv; hv.x = h0; hv.y = h1;
            __nv_bfloat162 lv;
            lv.x = __float2bfloat16(x0 - __bfloat162float(h0));
            lv.y = __float2bfloat16(x1 - __bfloat162float(h1));
            size_t row = (size_t)(i*DIM + f)*KE;
            int col = j*DIM + g0 + gp;
            *(__nv_bfloat162*)&g_Text[row + col]        = hv;
            *(__nv_bfloat162*)&g_Text[row + 2048 + col] = hv;
            *(__nv_bfloat162*)&g_Text[row + 4096 + col] = lv;
        }
        __syncthreads();
    }
}

__global__ void k_initRS() {
    int r = blockIdx.x, e = threadIdx.x;     // grid 2048 x 128
    g_S[(size_t)r*DIM + e] = (r == (NN - DIM) + e) ? 1.f : 0.f;
    if (r < DIM) {
#pragma unroll
        for (int it = 0; it < 24; it++) {
            int cp = (it*128 + e) * 2;
            int seg = cp >> 11, cc = cp & 2047;
            float v0 = ((seg == 0 || seg == 2) && cc     == (NN - DIM) + r) ? 1.f : 0.f;
            float v1 = ((seg == 0 || seg == 2) && cc + 1 == (NN - DIM) + r) ? 1.f : 0.f;
            __nv_bfloat162 v; v.x = __float2bfloat16(v0); v.y = __float2bfloat16(v1);
            *(__nv_bfloat162*)&g_Rt[0][(size_t)r*KE + cp] = v;
        }
    }
}

__global__ void k_reduce2(int cur, int addS) {
    const int mt = blockIdx.x, sl = blockIdx.y;
    const int base_r = mt*128 + sl*32;
    __shared__ float slab[32][DIM + 1];
    const int tid = threadIdx.x;
    for (int u = tid; u < 32*DIM; u += 256) {
        int rr = u >> 7, e = u & 127;
        float v = 0.f;
#pragma unroll
        for (int k = 0; k < KSPLIT; k++)
            v += g_P[(size_t)k*NN*DIM + (size_t)(base_r + rr)*DIM + e];
        g_Rf[(size_t)(base_r + rr)*DIM + e] = v;
        if (addS) g_S[(size_t)(base_r + rr)*DIM + e] += v;
        slab[rr][e] = v;
    }
    __syncthreads();
    int e = tid >> 1, hh = tid & 1;
    __nv_bfloat16* Rt = g_Rt[cur ^ 1];
#pragma unroll
    for (int k = 0; k < 16; k++) {
        int rr = hh*16 + k;
        float v = slab[rr][e];
        __nv_bfloat16 h = __float2bfloat16(v);
        __nv_bfloat16 l = __float2bfloat16(v - __bfloat162float(h));
        int col = base_r + rr;
        Rt[(size_t)e*KE + col]        = h;   // seg0: Rhi (pairs Thi)
        Rt[(size_t)e*KE + 2048 + col] = l;   // seg1: Rlo (pairs Thi)
        Rt[(size_t)e*KE + 4096 + col] = h;   // seg2: Rhi (pairs Tlo)
    }
}

__global__ void k_h(const float* __restrict__ bpre) {
    int e = blockIdx.x, tid = threadIdx.x;
    float s = 0.f;
    for (int r = tid; r < NN; r += 256) s += g_beta[r] * g_S[(size_t)r*DIM + e];
    if (tid < DIM) s += bpre[tid] * g_Rf[(size_t)tid*DIM + e];
    __shared__ float red[256];
    red[tid] = s;
    __syncthreads();
    for (int off = 128; off > 0; off >>= 1) {
        if (tid < off) red[tid] += red[tid + off];
        __syncthreads();
    }
    if (tid == 0) g_h[e] = red[0];
}

__global__ void k_T1() {
    int d = blockIdx.y;
    int q = blockIdx.x*128 + threadIdx.x;
    const float* __restrict__ Er = g_Rf + (size_t)d*DIM;
    float acc = 0.f;
#pragma unroll 8
    for (int e = 0; e < DIM; e++) acc += Er[e] * g_WpostT[e*OUTC + q];
    g_T1[d*OUTC + q] = acc;
}

__global__ void k_G(const float* __restrict__ Wpre) {
    int p = blockIdx.y;
    int q = blockIdx.x*128 + threadIdx.x;
    float acc = 0.f;
#pragma unroll 8
    for (int d = 0; d < DIM; d++) acc += Wpre[d*INC + p] * g_T1[d*OUTC + q];
    g_G[p*OUTC + q] = acc;
}

__global__ void k_dvec(const float* __restrict__ bpost) {
    int q = blockIdx.x*128 + threadIdx.x;
    float acc = bpost[q];
#pragma unroll 8
    for (int e = 0; e < DIM; e++) acc += g_h[e] * g_WpostT[e*OUTC + q];
    g_dvec[q] = acc;
}

__global__ void k_split_inp(const float* __restrict__ inp) {
    int b = blockIdx.x, tid = threadIdx.x;
#pragma unroll
    for (int it = 0; it < 2; it++) {
        int qp = (it*128 + tid) * 2;
        float2 x = *(const float2*)&inp[(size_t)b*INC + qp];
        __nv_bfloat16 h0 = __float2bfloat16(x.x);
        __nv_bfloat16 h1 = __float2bfloat16(x.y);
        __nv_bfloat162 hv; hv.x = h0; hv.y = h1;
        __nv_bfloat162 lv;
        lv.x = __float2bfloat16(x.x - __bfloat162float(h0));
        lv.y = __float2bfloat16(x.y - __bfloat162float(h1));
        size_t ro = (size_t)b*KEF;
        *(__nv_bfloat162*)&g_Iext[ro + qp]        = hv;
        *(__nv_bfloat162*)&g_Iext[ro + 512 + qp]  = hv;
        *(__nv_bfloat162*)&g_Iext[ro + 1024 + qp] = lv;
    }
}

__global__ void k_split_G() {
    int q = blockIdx.x;
    for (int p = threadIdx.x; p < INC; p += 128) {
        float x = g_G[(size_t)p*OUTC + q];
        __nv_bfloat16 h = __float2bfloat16(x);
        __nv_bfloat16 l = __float2bfloat16(x - __bfloat162float(h));
        size_t ro = (size_t)q*KEF;
        g_Gext[ro + p]        = h;
        g_Gext[ro + 512 + p]  = l;
        g_Gext[ro + 1024 + p] = h;
    }
}

// ---------------- launch ----------------
extern "C" void kernel_launch(void* const* d_in, const int* in_sizes, int n_in,
                              void* d_out, int out_size) {
    (void)in_sizes; (void)n_in; (void)out_size;
    const float* inp   = (const float*)d_in[0];
    const float* Wpre  = (const float*)d_in[1];
    const float* bpre  = (const float*)d_in[2];
    const float* W     = (const float*)d_in[3];
    const float* bl    = (const float*)d_in[4];
    const float* life  = (const float*)d_in[5];
    const float* Wpost = (const float*)d_in[6];
    const float* bpost = (const float*)d_in[7];
    float* out = (float*)d_out;

    cudaFuncSetAttribute(k_mma_step, cudaFuncAttributeMaxDynamicSharedMemorySize, SMEM_BYTES);
    cudaFuncSetAttribute(k_mma_fin,  cudaFuncAttributeMaxDynamicSharedMemorySize, SMEM_BYTES);

    k_make_T<<<dim3(NUM, NUM), 256>>>(W, life);          // idx 0
    k_initRS<<<NN, DIM>>>();                             // idx 1
    k_prep<<<NUM, DIM>>>(life, bl);                      // idx 2

    int cur = 0;
    for (int s = 0; s < STEPS; s++) {
        k_mma_step<<<dim3(KSPLIT, NUM), 512, SMEM_BYTES>>>(cur);  // idx 3 first (profiled 5)
        k_reduce2<<<dim3(NUM, 4), 256>>>(cur, (s < STEPS - 1) ? 1 : 0);
        cur ^= 1;
    }

    k_h<<<DIM, 256>>>(bpre);
    k_transpose<<<DIM, OUTC>>>(Wpost);
    k_T1<<<dim3(OUTC/128, DIM), 128>>>();
    k_G<<<dim3(OUTC/128, INC), 128>>>(Wpre);
    k_dvec<<<OUTC/128, 128>>>(bpost);
    k_split_inp<<<BATCH, 128>>>(inp);
    k_split_G<<<OUTC, 128>>>();
    k_mma_fin<<<dim3(OUTC/128, BATCH/128), 512, SMEM_BYTES>>>(out);
}

// round 11
// speedup vs baseline: 1.6011x; 1.0454x over previous
#include <cuda_runtime.h>
#include <cuda_bf16.h>
#include <cstdint>

#define NUM 16
#define DIM 128
#define NN (NUM*DIM)            // 2048
#define BATCH 4096
#define INC 512
#define OUTC 512
#define STEPS 10
#define KP 4096                 // physical K, step chain: [Thi|Tlo] / [Rhi|Rlo]
#define KPF 1024                // physical K, final: [Ihi|Ilo] / [Ghi|Glo]
#define KSPLIT 8
#define BK 64
#define NSTAGE 5
#define RSW 36                  // smem row stride in words (32 data + 4 pad)
#define STG_W (128*RSW*2)       // words per stage (A+B) = 9216
#define SMEM_BYTES (NSTAGE*STG_W*4)   // 184320

// ---------------- device scratch ----------------
__device__ __align__(16) __nv_bfloat16 g_Text[NN*KP];        // [Thi|Tlo], 16.8MB
__device__ __align__(16) __nv_bfloat16 g_Rt[2][DIM*KP];      // [Rhi|Rlo] transposed
__device__ __align__(16) float g_P[KSPLIT*NN*DIM];           // split-K partials, 8.4MB
__device__ __align__(16) float g_S[NN*DIM];
__device__ __align__(16) float g_Rf[NN*DIM];
__device__ __align__(16) __nv_bfloat16 g_Iext[BATCH*KPF];    // [Ihi|Ilo], 8.4MB
__device__ __align__(16) __nv_bfloat16 g_Gext[OUTC*KPF];     // rows q: [Ghi|Glo] over p
__device__ __align__(16) float g_beta[NN];
__device__ __align__(16) float g_h[DIM];
__device__ __align__(16) float g_WpostT[DIM*OUTC];
__device__ __align__(16) float g_T1[DIM*OUTC];
__device__ __align__(16) float g_G[INC*OUTC];
__device__ __align__(16) float g_dvec[OUTC];

// ---------------- helpers ----------------
__device__ __forceinline__ void mma16816(float* d, const uint32_t* a, uint32_t b0, uint32_t b1) {
    asm volatile(
        "mma.sync.aligned.m16n8k16.row.col.f32.bf16.bf16.f32 "
        "{%0,%1,%2,%3}, {%4,%5,%6,%7}, {%8,%9}, {%0,%1,%2,%3};"
        : "+f"(d[0]), "+f"(d[1]), "+f"(d[2]), "+f"(d[3])
        : "r"(a[0]), "r"(a[1]), "r"(a[2]), "r"(a[3]), "r"(b0), "r"(b1));
}
__device__ __forceinline__ void ldsm4(uint32_t* r, uint32_t addr) {
    asm volatile("ldmatrix.sync.aligned.m8n8.x4.shared.b16 {%0,%1,%2,%3}, [%4];"
                 : "=r"(r[0]), "=r"(r[1]), "=r"(r[2]), "=r"(r[3]) : "r"(addr));
}
__device__ __forceinline__ void cpa16(uint32_t saddr, const void* g) {
    asm volatile("cp.async.ca.shared.global [%0], [%1], 16;" :: "r"(saddr), "l"(g));
}
__device__ __forceinline__ void cpa_commit() { asm volatile("cp.async.commit_group;" ::: "memory"); }
template<int N> __device__ __forceinline__ void cpa_wait() {
    asm volatile("cp.async.wait_group %0;" :: "n"(N) : "memory");
}
__device__ __forceinline__ uint32_t smem_u32(const void* p) {
    uint32_t a;
    asm("{ .reg .u64 t; cvta.to.shared.u64 t, %1; cvt.u32.u64 %0, t; }" : "=r"(a) : "l"(p));
    return a;
}

// ---------------- GEMM body with virtual->physical K-chunk mapping -------------------------
// Virtual K = 3 segments of SEGC chunks each; physical arrays hold 2 segments.
//   A chunk: vseg 0,1 -> phys seg 0 (hi); vseg 2 -> phys seg 1 (lo)
//   B chunk: vseg 0,2 -> phys seg 0 (hi); vseg 1 -> phys seg 1 (lo)
// 512 threads, 16 warps, warp tile 32x32; BK=64; NSTAGE-deep cp.async pipeline.
template<int SEGC, bool BIAS>
__device__ __forceinline__ void gemm_cp(const __nv_bfloat16* __restrict__ Ag, long ldA,
                                        const __nv_bfloat16* __restrict__ Bg, long ldB,
                                        int vcBase, int nch,
                                        float* __restrict__ Out, long ldo,
                                        const float* __restrict__ bias) {
    extern __shared__ __align__(16) uint32_t sm[];
    const uint32_t sbase = smem_u32(sm);
    const int tid = threadIdx.x, wid = tid >> 5, lane = tid & 31;
    const int g = lane >> 2, tc = lane & 3;
    const int wr0 = (wid & 3) * 32, wc0 = (wid >> 2) * 32;

    float acc[2][4][4];
#pragma unroll
    for (int f = 0; f < 2; f++)
#pragma unroll
        for (int nf = 0; nf < 4; nf++)
#pragma unroll
            for (int v = 0; v < 4; v++) acc[f][nf][v] = 0.f;

    // ldmatrix per-lane bases (byte units within a stage)
    const int q = lane >> 3, r8 = lane & 7;
    uint32_t aB[2], bB[2];
#pragma unroll
    for (int f = 0; f < 2; f++)
        aB[f] = (uint32_t)(((wr0 + f*16 + r8 + (q & 1)*8)*RSW + (q >> 1)*4) * 4);
#pragma unroll
    for (int n4 = 0; n4 < 2; n4++)
        bB[n4] = (uint32_t)(((128 + wc0 + n4*16 + r8 + (q >> 1)*8)*RSW + (q & 1)*4) * 4);

    // cp.async mapping: tid<256 -> A rows, tid>=256 -> B rows; 64B/thread per stage
    const int isB = tid >= 256, lt = tid & 255;
    const int Lr = lt >> 1, offw = (lt & 1)*16;
    const __nv_bfloat16* __restrict__ Gsrc = isB ? Bg : Ag;
    const long ldS = isB ? ldB : ldA;
    const uint32_t dBase = sbase + (uint32_t)(((isB ? 128*RSW : 0) + Lr*RSW + offw) * 4);

    auto load_stage = [&](int c, int s) {
        int vc = vcBase + c;
        int m = vc & (SEGC - 1);
        int ac = (vc < 2*SEGC) ? m : SEGC + m;
        int bc = (vc < SEGC) ? vc : ((vc < 2*SEGC) ? SEGC + m : m);
        int ci = isB ? bc : ac;
        const __nv_bfloat16* gp = Gsrc + (long)Lr*ldS + (long)ci*BK + offw*2;
        uint32_t d = dBase + (uint32_t)(s*STG_W*4);
        cpa16(d, gp); cpa16(d + 16, gp + 8);
        cpa16(d + 32, gp + 16); cpa16(d + 48, gp + 24);
        cpa_commit();
    };

    int ls = 0;
#pragma unroll
    for (int p = 0; p < NSTAGE - 1; p++) {
        load_stage(p, ls);
        if (++ls == NSTAGE) ls = 0;
    }

    uint32_t af[2][2][4], bf[2][2][4];

#define LD_FR(kk, buf, stg) do {                                                  \
        uint32_t _kw = (uint32_t)((kk)*32);                                       \
        ldsm4(af[buf][0], (stg) + aB[0] + _kw);                                   \
        ldsm4(af[buf][1], (stg) + aB[1] + _kw);                                   \
        ldsm4(bf[buf][0], (stg) + bB[0] + _kw);                                   \
        ldsm4(bf[buf][1], (stg) + bB[1] + _kw);                                   \
    } while (0)

#define DO_MMA(buf) do {                                                          \
        _Pragma("unroll")                                                         \
        for (int n4 = 0; n4 < 2; n4++) {                                          \
            mma16816(acc[0][n4*2],     af[buf][0], bf[buf][n4][0], bf[buf][n4][1]); \
            mma16816(acc[1][n4*2],     af[buf][1], bf[buf][n4][0], bf[buf][n4][1]); \
            mma16816(acc[0][n4*2 + 1], af[buf][0], bf[buf][n4][2], bf[buf][n4][3]); \
            mma16816(acc[1][n4*2 + 1], af[buf][1], bf[buf][n4][2], bf[buf][n4][3]); \
        }                                                                         \
    } while (0)

    int cs = 0;
    for (int ch = 0; ch < nch; ch++) {
        const int rem = nch - 1 - ch;
        if (rem >= 3) cpa_wait<3>();
        else if (rem == 2) cpa_wait<2>();
        else if (rem == 1) cpa_wait<1>();
        else cpa_wait<0>();
        __syncthreads();
        if (ch + NSTAGE - 1 < nch) {
            load_stage(ch + NSTAGE - 1, ls);
            if (++ls == NSTAGE) ls = 0;
        }
        const uint32_t stg = sbase + (uint32_t)(cs*STG_W*4);
        if (++cs == NSTAGE) cs = 0;
        LD_FR(0, 0, stg);
        LD_FR(1, 1, stg);
        DO_MMA(0);
        LD_FR(2, 0, stg);
        DO_MMA(1);
        LD_FR(3, 1, stg);
        DO_MMA(0);
        DO_MMA(1);
    }
#undef LD_FR
#undef DO_MMA
#pragma unroll
    for (int f = 0; f < 2; f++) {
        const int row0 = wr0 + f*16 + g;
#pragma unroll
        for (int nf = 0; nf < 4; nf++) {
            const int col = wc0 + nf*8 + tc*2;
            float2 v0 = make_float2(acc[f][nf][0], acc[f][nf][1]);
            float2 v1 = make_float2(acc[f][nf][2], acc[f][nf][3]);
            if (BIAS) {
                float2 d = *(const float2*)&bias[col];
                v0.x += d.x; v0.y += d.y; v1.x += d.x; v1.y += d.y;
            }
            *(float2*)(Out + (long)row0*ldo + col)       = v0;
            *(float2*)(Out + (long)(row0 + 8)*ldo + col) = v1;
        }
    }
}

// step MMA: virtual K=6144 over [Thi|Thi|Tlo] x [Rhi|Rlo|Rhi]; 12 virtual chunks per slice
__global__ void __launch_bounds__(512, 1) k_mma_step(int cur) {
    const int ks = blockIdx.x, mt = blockIdx.y;
    gemm_cp<32, false>(g_Text + (size_t)mt*128*KP, KP,
                       g_Rt[cur], KP,
                       ks*12, 12,
                       g_P + ((size_t)ks*NN + mt*128)*DIM, DIM, nullptr);
}

// final MMA: virtual K=1536 over [Ihi|Ihi|Ilo] x [Ghi|Glo|Ghi]; bias fused
__global__ void __launch_bounds__(512, 1) k_mma_fin(float* __restrict__ out) {
    const int qt = blockIdx.x, bt = blockIdx.y;
    gemm_cp<8, true>(g_Iext + (size_t)bt*128*KPF, KPF,
                     g_Gext + (size_t)qt*128*KPF, KPF,
                     0, 24,
                     out + (size_t)bt*128*OUTC + qt*128, OUTC, g_dvec + qt*128);
}

// ---------------- prep kernels ----------------

__global__ void k_prep(const float* __restrict__ life, const float* __restrict__ bl) {
    int j = blockIdx.x, g = threadIdx.x;
    float s = 0.f;
#pragma unroll
    for (int i = 0; i < NUM; i++) {
        float gt = fmaxf(life[i*NUM + j], 0.f);
        s += gt * bl[(i*NUM + j)*DIM + g];
    }
    g_beta[j*DIM + g] = s;
}

__global__ void k_transpose(const float* __restrict__ Wpost) {
    int e = blockIdx.x, q = threadIdx.x;
    g_WpostT[e*OUTC + q] = Wpost[q*DIM + e];
}

// T phys [Thi|Tlo] of gate*W (cols 0-2047 hi, 2048-4095 lo)
__global__ void k_make_T(const float* __restrict__ W, const float* __restrict__ life) {
    const int j = blockIdx.x, i = blockIdx.y;
    const float gate = fmaxf(life[i*NUM + j], 0.f);
    const float* __restrict__ Wb = W + (size_t)(i*NUM + j)*DIM*DIM;   // [g][f]
    __shared__ float sm[32][DIM + 1];
    const int tid = threadIdx.x;
    for (int g0 = 0; g0 < DIM; g0 += 32) {
        for (int u = tid; u < 32*DIM; u += 256) {
            int gg = u >> 7, f = u & 127;
            sm[gg][f] = Wb[(size_t)(g0 + gg)*DIM + f];
        }
        __syncthreads();
#pragma unroll
        for (int it = 0; it < 8; it++) {
            int pi = it*256 + tid;
            int f = pi >> 4, gp = (pi & 15) * 2;
            float x0 = gate * sm[gp][f];
            float x1 = gate * sm[gp + 1][f];
            __nv_bfloat16 h0 = __float2bfloat16(x0);
            __nv_bfloat16 h1 = __float2bfloat16(x1);
            __nv_bfloat162 hv; hv.x = h0; hv.y = h1;
            __nv_bfloat162 lv;
            lv.x = __float2bfloat16(x0 - __bfloat162float(h0));
            lv.y = __float2bfloat16(x1 - __bfloat162float(h1));
            size_t row = (size_t)(i*DIM + f)*KP;
            int col = j*DIM + g0 + gp;
            *(__nv_bfloat162*)&g_Text[row + col]        = hv;
            *(__nv_bfloat162*)&g_Text[row + 2048 + col] = lv;
        }
        __syncthreads();
    }
}

// Rt[0] phys: [Rhi identity | Rlo = 0]; S = R_0
__global__ void k_initRS() {
    int r = blockIdx.x, e = threadIdx.x;     // grid 2048 x 128
    g_S[(size_t)r*DIM + e] = (r == (NN - DIM) + e) ? 1.f : 0.f;
    if (r < DIM) {
#pragma unroll
        for (int it = 0; it < 16; it++) {
            int cp = (it*128 + e) * 2;       // col pair over KP=4096
            float v0 = (cp < 2048 && cp     == (NN - DIM) + r) ? 1.f : 0.f;
            float v1 = (cp < 2048 && cp + 1 == (NN - DIM) + r) ? 1.f : 0.f;
            __nv_bfloat162 v; v.x = __float2bfloat16(v0); v.y = __float2bfloat16(v1);
            *(__nv_bfloat162*)&g_Rt[0][(size_t)r*KP + cp] = v;
        }
    }
}

// reduce split-K partials -> Rf, S accum, re-split transposed into Rt[cur^1] [Rhi|Rlo]
__global__ void k_reduce2(int cur, int addS) {
    const int mt = blockIdx.x, sl = blockIdx.y;
    const int base_r = mt*128 + sl*32;
    __shared__ float slab[32][DIM + 1];
    const int tid = threadIdx.x;
    for (int u = tid; u < 32*DIM; u += 256) {
        int rr = u >> 7, e = u & 127;
        float v = 0.f;
#pragma unroll
        for (int k = 0; k < KSPLIT; k++)
            v += g_P[(size_t)k*NN*DIM + (size_t)(base_r + rr)*DIM + e];
        g_Rf[(size_t)(base_r + rr)*DIM + e] = v;
        if (addS) g_S[(size_t)(base_r + rr)*DIM + e] += v;
        slab[rr][e] = v;
    }
    __syncthreads();
    int e = tid >> 1, hh = tid & 1;
    __nv_bfloat16* Rt = g_Rt[cur ^ 1];
#pragma unroll
    for (int k = 0; k < 16; k++) {
        int rr = hh*16 + k;
        float v = slab[rr][e];
        __nv_bfloat16 h = __float2bfloat16(v);
        __nv_bfloat16 l = __float2bfloat16(v - __bfloat162float(h));
        int col = base_r + rr;
        Rt[(size_t)e*KP + col]        = h;   // Rhi
        Rt[(size_t)e*KP + 2048 + col] = l;   // Rlo
    }
}

__global__ void k_h(const float* __restrict__ bpre) {
    int e = blockIdx.x, tid = threadIdx.x;
    float s = 0.f;
    for (int r = tid; r < NN; r += 256) s += g_beta[r] * g_S[(size_t)r*DIM + e];
    if (tid < DIM) s += bpre[tid] * g_Rf[(size_t)tid*DIM + e];
    __shared__ float red[256];
    red[tid] = s;
    __syncthreads();
    for (int off = 128; off > 0; off >>= 1) {
        if (tid < off) red[tid] += red[tid + off];
        __syncthreads();
    }
    if (tid == 0) g_h[e] = red[0];
}

__global__ void k_T1() {
    int d = blockIdx.y;
    int q = blockIdx.x*128 + threadIdx.x;
    const float* __restrict__ Er = g_Rf + (size_t)d*DIM;
    float acc = 0.f;
#pragma unroll 8
    for (int e = 0; e < DIM; e++) acc += Er[e] * g_WpostT[e*OUTC + q];
    g_T1[d*OUTC + q] = acc;
}

__global__ void k_G(const float* __restrict__ Wpre) {
    int p = blockIdx.y;
    int q = blockIdx.x*128 + threadIdx.x;
    float acc = 0.f;
#pragma unroll 8
    for (int d = 0; d < DIM; d++) acc += Wpre[d*INC + p] * g_T1[d*OUTC + q];
    g_G[p*OUTC + q] = acc;
}

__global__ void k_dvec(const float* __restrict__ bpost) {
    int q = blockIdx.x*128 + threadIdx.x;
    float acc = bpost[q];
#pragma unroll 8
    for (int e = 0; e < DIM; e++) acc += g_h[e] * g_WpostT[e*OUTC + q];
    g_dvec[q] = acc;
}

// inp -> phys [Ihi|Ilo]
__global__ void k_split_inp(const float* __restrict__ inp) {
    int b = blockIdx.x, tid = threadIdx.x;
#pragma unroll
    for (int it = 0; it < 2; it++) {
        int qp = (it*128 + tid) * 2;
        float2 x = *(const float2*)&inp[(size_t)b*INC + qp];
        __nv_bfloat16 h0 = __float2bfloat16(x.x);
        __nv_bfloat16 h1 = __float2bfloat16(x.y);
        __nv_bfloat162 hv; hv.x = h0; hv.y = h1;
        __nv_bfloat162 lv;
        lv.x = __float2bfloat16(x.x - __bfloat162float(h0));
        lv.y = __float2bfloat16(x.y - __bfloat162float(h1));
        size_t ro = (size_t)b*KPF;
        *(__nv_bfloat162*)&g_Iext[ro + qp]       = hv;
        *(__nv_bfloat162*)&g_Iext[ro + 512 + qp] = lv;
    }
}

// Gext row q over p: phys [Ghi|Glo] of G[p][q]
__global__ void k_split_G() {
    int q = blockIdx.x;
    for (int p = threadIdx.x; p < INC; p += 128) {
        float x = g_G[(size_t)p*OUTC + q];
        __nv_bfloat16 h = __float2bfloat16(x);
        __nv_bfloat16 l = __float2bfloat16(x - __bfloat162float(h));
        size_t ro = (size_t)q*KPF;
        g_Gext[ro + p]       = h;
        g_Gext[ro + 512 + p] = l;
    }
}

// ---------------- launch ----------------
extern "C" void kernel_launch(void* const* d_in, const int* in_sizes, int n_in,
                              void* d_out, int out_size) {
    (void)in_sizes; (void)n_in; (void)out_size;
    const float* inp   = (const float*)d_in[0];
    const float* Wpre  = (const float*)d_in[1];
    const float* bpre  = (const float*)d_in[2];
    const float* W     = (const float*)d_in[3];
    const float* bl    = (const float*)d_in[4];
    const float* life  = (const float*)d_in[5];
    const float* Wpost = (const float*)d_in[6];
    const float* bpost = (const float*)d_in[7];
    float* out = (float*)d_out;

    cudaFuncSetAttribute(k_mma_step, cudaFuncAttributeMaxDynamicSharedMemorySize, SMEM_BYTES);
    cudaFuncSetAttribute(k_mma_fin,  cudaFuncAttributeMaxDynamicSharedMemorySize, SMEM_BYTES);

    k_make_T<<<dim3(NUM, NUM), 256>>>(W, life);          // idx 0
    k_initRS<<<NN, DIM>>>();                             // idx 1
    k_prep<<<NUM, DIM>>>(life, bl);                      // idx 2

    int cur = 0;
    for (int s = 0; s < STEPS; s++) {
        k_mma_step<<<dim3(KSPLIT, NUM), 512, SMEM_BYTES>>>(cur);  // idx 3 first (profiled 5)
        k_reduce2<<<dim3(NUM, 4), 256>>>(cur, (s < STEPS - 1) ? 1 : 0);
        cur ^= 1;
    }

    k_h<<<DIM, 256>>>(bpre);
    k_transpose<<<DIM, OUTC>>>(Wpost);
    k_T1<<<dim3(OUTC/128, DIM), 128>>>();
    k_G<<<dim3(OUTC/128, INC), 128>>>(Wpre);
    k_dvec<<<OUTC/128, 128>>>(bpost);
    k_split_inp<<<BATCH, 128>>>(inp);
    k_split_G<<<OUTC, 128>>>();
    k_mma_fin<<<dim3(OUTC/128, BATCH/128), 512, SMEM_BYTES>>>(out);
}